// round 10
// baseline (speedup 1.0000x reference)
#include <cuda_runtime.h>
#include <math.h>

#define KC 64
#define DD 8
#define NC 36
#define CP 46          // ull entries per k-PAIR: 36 A + 8 nw + 1 c2n + 1 pad
#define NKP (KC / 2)   // 32 k-pairs
#define NBLOCKS 256
#define TX 128
#define TY 4
#define NTHREADS (TX * TY)
#define BTOT 131072

typedef unsigned long long ull;

__device__ __align__(16) ull g_coeffp[NKP * CP];
__device__ float g_partials[NBLOCKS];
__device__ unsigned g_count = 0;

__device__ __forceinline__ float ex2f(float x) {
    float y; asm("ex2.approx.ftz.f32 %0, %1;" : "=f"(y) : "f"(x)); return y;
}
__device__ __forceinline__ float lg2f(float x) {
    float y; asm("lg2.approx.f32 %0, %1;" : "=f"(y) : "f"(x)); return y;
}
__device__ __forceinline__ ull fma2(ull a, ull b, ull c) {
    ull d; asm("fma.rn.f32x2 %0, %1, %2, %3;" : "=l"(d) : "l"(a), "l"(b), "l"(c)); return d;
}
__device__ __forceinline__ ull pack2(float lo, float hi) {
    ull v; asm("mov.b64 %0, {%1, %2};" : "=l"(v) : "f"(lo), "f"(hi)); return v;
}
__device__ __forceinline__ void unpack2(float& lo, float& hi, ull v) {
    asm("mov.b64 {%0, %1}, %2;" : "=f"(lo), "=f"(hi) : "l"(v));
}

// ---------------------------------------------------------------------------
// Prep (fp32): per k, A = L^{-1}*sqrt(0.5/ln2), nw = -A@mu,
// c2n = sum(log2 Lii) + 4*log2(2pi). Then pack k-PAIRS: lane=(k_even,k_odd).
// ---------------------------------------------------------------------------
__global__ void prep_kernel(const float* __restrict__ mu,
                            const float* __restrict__ Lc) {
    __shared__ float sbuf[KC][CP];
    int k = threadIdx.x;
    if (k < KC) {
        float L[DD][DD];
        int m = 0;
#pragma unroll
        for (int i = 0; i < DD; i++)
#pragma unroll
            for (int j = 0; j <= i; j++)
                L[i][j] = Lc[k * NC + m++];

        float X[DD][DD];
#pragma unroll
        for (int j = 0; j < DD; j++) {
            X[j][j] = 1.0f / L[j][j];
#pragma unroll
            for (int i = j + 1; i < DD; i++) {
                float s = 0.0f;
                for (int t = j; t < i; t++) s = fmaf(L[i][t], X[t][j], s);
                X[i][j] = -s / L[i][i];
            }
        }
        float sumlg2 = 0.0f;
#pragma unroll
        for (int i = 0; i < DD; i++) sumlg2 += lg2f(L[i][i]);

        const float SCALE = 0.8493218003f;        // sqrt(0.5/ln2)
        const float C4LOG2PI = 10.6059845179f;    // 4*log2(2*pi)

        m = 0;
#pragma unroll
        for (int i = 0; i < DD; i++)
#pragma unroll
            for (int j = 0; j <= i; j++)
                sbuf[k][m++] = X[i][j] * SCALE;
#pragma unroll
        for (int i = 0; i < DD; i++) {
            float acc = 0.0f;
#pragma unroll
            for (int j = 0; j <= i; j++) acc = fmaf(X[i][j], mu[k * DD + j], acc);
            sbuf[k][36 + i] = -SCALE * acc;
        }
        sbuf[k][44] = sumlg2 + C4LOG2PI;
        sbuf[k][45] = 0.0f;
    }
    __syncthreads();
    if (k < NKP) {
#pragma unroll
        for (int m = 0; m < CP; m++)
            g_coeffp[k * CP + m] = pack2(sbuf[2 * k][m], sbuf[2 * k + 1][m]);
    }
}

// compile-time idx -> LDS.128 half (pairs merge into vec loads, CSE'd)
#define CPAIR(cq, idx) (((idx) & 1) ? (cq)[(idx) >> 1].y : (cq)[(idx) >> 1].x)

// ---------------------------------------------------------------------------
// Main: block (128,4). Each y-slice processes 16 of the 64 components for the
// SAME 4 rows; slices merge partial logsumexp states via smem. f32x2 lanes
// carry (k_even,k_odd). Pairwise-batched online logsumexp epilogue.
// ---------------------------------------------------------------------------
__global__ void __launch_bounds__(NTHREADS)
main_kernel(const float* __restrict__ pi, const float* __restrict__ target,
            float* __restrict__ out) {
    __shared__ __align__(16) ull sc[NKP * CP];        // 11.5 KB
    __shared__ float s_mx[TY - 1][TX][4];             // merge buffers (6 KB)
    __shared__ float s_sm[TY - 1][TX][4];
    __shared__ float red[NTHREADS];
    __shared__ bool s_last;

    const int tid = threadIdx.x;
    const int ys = threadIdx.y;
    const int flat = ys * TX + tid;

    {
        const float4* gsrc = (const float4*)g_coeffp;
        float4* sdst = (float4*)sc;
#pragma unroll
        for (int i = flat; i < NKP * CP / 2; i += NTHREADS)
            sdst[i] = gsrc[i];
    }
    __syncthreads();

    const int b0 = blockIdx.x * (TX * 4) + tid;

    // 4 target rows, each component duplicated into both f32x2 lanes
    ull tpd[4][DD];
#pragma unroll
    for (int r = 0; r < 4; r++) {
        const float4* tp4 = (const float4*)(target + (size_t)(b0 + r * TX) * DD);
        float4 v0 = tp4[0], v1 = tp4[1];
        tpd[r][0] = pack2(v0.x, v0.x); tpd[r][1] = pack2(v0.y, v0.y);
        tpd[r][2] = pack2(v0.z, v0.z); tpd[r][3] = pack2(v0.w, v0.w);
        tpd[r][4] = pack2(v1.x, v1.x); tpd[r][5] = pack2(v1.y, v1.y);
        tpd[r][6] = pack2(v1.z, v1.z); tpd[r][7] = pack2(v1.w, v1.w);
    }

    float mx[4], sm[4];
#pragma unroll
    for (int r = 0; r < 4; r++) { mx[r] = -1e30f; sm[r] = 0.0f; }

    // this slice's k range: tiles of 4 k (= 2 k-pairs); 4 tiles per slice
#pragma unroll 1
    for (int kt = ys * (KC / 16); kt < (ys + 1) * (KC / 16); kt++) {
        float p[4][4];
#pragma unroll
        for (int r = 0; r < 4; r++) {
            float4 pv = *((const float4*)(pi + (size_t)(b0 + r * TX) * KC + kt * 4));
            p[r][0] = pv.x; p[r][1] = pv.y; p[r][2] = pv.z; p[r][3] = pv.w;
        }
#pragma unroll
        for (int qq = 0; qq < 2; qq++) {
            const ulonglong2* cq = (const ulonglong2*)(sc + (kt * 2 + qq) * CP);

            ull a[4], macc[4];
            {
                ull nw = CPAIR(cq, 36);
                ull c0 = CPAIR(cq, 0);
                ull c2 = CPAIR(cq, 44);
#pragma unroll
                for (int r = 0; r < 4; r++) a[r] = fma2(c0, tpd[r][0], nw);
#pragma unroll
                for (int r = 0; r < 4; r++) macc[r] = fma2(a[r], a[r], c2);
            }
            int m = 1;
#pragma unroll
            for (int i = 1; i < DD; i++) {
                ull nw = CPAIR(cq, 36 + i);
                ull cj0 = CPAIR(cq, m);
#pragma unroll
                for (int r = 0; r < 4; r++) a[r] = fma2(cj0, tpd[r][0], nw);
#pragma unroll
                for (int j = 1; j <= i; j++) {
                    ull cc = CPAIR(cq, m + j);
#pragma unroll
                    for (int r = 0; r < 4; r++) a[r] = fma2(cc, tpd[r][j], a[r]);
                }
                m += i + 1;
#pragma unroll
                for (int r = 0; r < 4; r++) macc[r] = fma2(a[r], a[r], macc[r]);
            }

#pragma unroll
            for (int r = 0; r < 4; r++) {
                float mm0, mm1;
                unpack2(mm0, mm1, macc[r]);
                // pairwise batch: combine the 2 k's of this kpair first
                float w0 = lg2f(p[r][qq * 2 + 0] + 1e-10f) - mm0;
                float w1 = lg2f(p[r][qq * 2 + 1] + 1e-10f) - mm1;
                float dm = w0 - w1;
                float e01 = ex2f(fminf(dm, -dm));     // 2^(-|w0-w1|)
                float m01 = fmaxf(w0, w1);
                float s01 = 1.0f + e01;
                // merge (m01, s01) into the running state
                float d2 = m01 - mx[r];
                float e2 = ex2f(fminf(d2, -d2));      // 2^(-|d2|)
                float shi = fmaf(sm[r], e2, s01);     // new max path
                float slo = fmaf(s01, e2, sm[r]);     // old max path
                sm[r] = (d2 > 0.0f) ? shi : slo;
                mx[r] = fmaxf(mx[r], m01);
            }
        }
    }

    // merge the 4 y-slices: ys>0 publish, ys==0 combines
    if (ys > 0) {
#pragma unroll
        for (int r = 0; r < 4; r++) {
            s_mx[ys - 1][tid][r] = mx[r];
            s_sm[ys - 1][tid][r] = sm[r];
        }
    }
    __syncthreads();

    float part = 0.0f;
    if (ys == 0) {
#pragma unroll
        for (int r = 0; r < 4; r++) {
            float M = mx[r], S = sm[r];
#pragma unroll
            for (int h = 0; h < TY - 1; h++) {
                float m2 = s_mx[h][tid][r], s2 = s_sm[h][tid][r];
                float mn = fmaxf(M, m2);
                S = fmaf(S, ex2f(M - mn), s2 * ex2f(m2 - mn));
                M = mn;
            }
            part += M + lg2f(S);
        }
    }

    red[flat] = part;
    __syncthreads();
#pragma unroll
    for (int s = NTHREADS / 2; s > 0; s >>= 1) {
        if (flat < s) red[flat] += red[flat + s];
        __syncthreads();
    }
    if (flat == 0) {
        g_partials[blockIdx.x] = red[0];
        __threadfence();
        unsigned done = atomicAdd(&g_count, 1u);
        s_last = (done == NBLOCKS - 1);
    }
    __syncthreads();

    if (s_last) {
        float v = (flat < NBLOCKS) ? g_partials[flat] : 0.0f;
        red[flat] = v;
        __syncthreads();
#pragma unroll
        for (int s = NTHREADS / 2; s > 0; s >>= 1) {
            if (flat < s) red[flat] += red[flat + s];
            __syncthreads();
        }
        if (flat == 0) {
            out[0] = (float)(-0.6931471805599453 * (double)red[0] / (double)BTOT);
            g_count = 0;   // reset for next graph replay
        }
    }
}

extern "C" void kernel_launch(void* const* d_in, const int* in_sizes, int n_in,
                              void* d_out, int out_size) {
    const float* pi = (const float*)d_in[0];
    const float* mu = (const float*)d_in[1];
    const float* Lc = (const float*)d_in[2];
    const float* target = (const float*)d_in[3];

    prep_kernel<<<1, KC>>>(mu, Lc);
    dim3 blk(TX, TY);
    main_kernel<<<NBLOCKS, blk>>>(pi, target, (float*)d_out);
}